// round 1
// baseline (speedup 1.0000x reference)
#include <cuda_runtime.h>

#define NQ 8
#define DIM 256
#define NCOL 16
#define NPAIR 136
#define BATCH 65536

// Scratch (computed per launch from params; no allocations allowed)
__device__ float2 g_M[NCOL][DIM];     // 16 columns of the variational unitary
__device__ float  g_B[NPAIR * 8];     // packed symmetric quadratic forms (pair-major, 8 outputs)

// ---------------------------------------------------------------------------
// S1: simulate the variational circuit on the 16 relevant basis columns.
// One block per column, 128 threads = 128 amplitude-pairs per gate.
// ---------------------------------------------------------------------------
__device__ __forceinline__ void apply_gate(float2* st, int bit, int t,
                                           float2 g00, float2 g01,
                                           float2 g10, float2 g11) {
    __syncthreads();
    int j0 = ((t & ~(bit - 1)) << 1) | (t & (bit - 1));
    int j1 = j0 | bit;
    float2 a0 = st[j0], a1 = st[j1];
    float2 n0, n1;
    n0.x = g00.x * a0.x - g00.y * a0.y + g01.x * a1.x - g01.y * a1.y;
    n0.y = g00.x * a0.y + g00.y * a0.x + g01.x * a1.y + g01.y * a1.x;
    n1.x = g10.x * a0.x - g10.y * a0.y + g11.x * a1.x - g11.y * a1.y;
    n1.y = g10.x * a0.y + g10.y * a0.x + g11.x * a1.y + g11.y * a1.x;
    st[j0] = n0;
    st[j1] = n1;
}

__device__ __forceinline__ void apply_cnot(float2* st, int c, int t) {
    __syncthreads();
    if (t < 64) {
        int cb = 1 << (7 - c);      // control bit (wire c)
        int tb = cb >> 1;           // target bit (wire c+1, adjacent)
        int low = t & (tb - 1);
        int high = (t & ~(tb - 1)) << 2;
        int j = high | cb | low;    // control=1, target=0
        float2 a = st[j], b = st[j | tb];
        st[j] = b;
        st[j | tb] = a;
    }
}

__global__ void setup_columns(const float* __restrict__ params) {
    __shared__ float2 st[DIM];
    int t = threadIdx.x;            // 0..127
    int col = blockIdx.x;           // 0..15
    st[t] = make_float2(0.f, 0.f);
    st[t + 128] = make_float2(0.f, 0.f);
    __syncthreads();
    if (t == 0) st[col * 16] = make_float2(1.f, 0.f);

    for (int layer = 0; layer < 2; ++layer) {
        for (int w = 0; w < NQ; ++w) {
            const float* p = params + layer * 24 + w * 3;
            int bit = 1 << (7 - w);
            float sh, ch;
            // RX
            sincosf(0.5f * p[0], &sh, &ch);
            apply_gate(st, bit, t,
                       make_float2(ch, 0.f), make_float2(0.f, -sh),
                       make_float2(0.f, -sh), make_float2(ch, 0.f));
            // RY
            sincosf(0.5f * p[1], &sh, &ch);
            apply_gate(st, bit, t,
                       make_float2(ch, 0.f), make_float2(-sh, 0.f),
                       make_float2(sh, 0.f), make_float2(ch, 0.f));
            // RZ
            sincosf(0.5f * p[2], &sh, &ch);
            apply_gate(st, bit, t,
                       make_float2(ch, -sh), make_float2(0.f, 0.f),
                       make_float2(0.f, 0.f), make_float2(ch, sh));
        }
        for (int c = 0; c < NQ - 1; ++c) apply_cnot(st, c, t);
    }
    __syncthreads();
    g_M[col][t] = st[t];
    g_M[col][t + 128] = st[t + 128];
}

// ---------------------------------------------------------------------------
// S2: B_i[k,l] = Re( i^(popc(k)-popc(l)) * sum_j sign_i(j) conj(M[j,k]) M[j,l] )
// thread = (i, k, l); only k<=l written, off-diagonal doubled.
// ---------------------------------------------------------------------------
__global__ void setup_B() {
    int gid = blockIdx.x * 128 + threadIdx.x;   // 0..2047
    int i = gid >> 8;
    int k = (gid >> 4) & 15;
    int l = gid & 15;
    float ar = 0.f, ai = 0.f;
    int shift = 7 - i;
    for (int j = 0; j < DIM; ++j) {
        float2 mk = g_M[k][j];
        float2 ml = g_M[l][j];
        float pr = mk.x * ml.x + mk.y * ml.y;   // conj(mk)*ml
        float pi = mk.x * ml.y - mk.y * ml.x;
        float sg = ((j >> shift) & 1) ? -1.f : 1.f;
        ar += sg * pr;
        ai += sg * pi;
    }
    if (k <= l) {
        int d = (__popc(k) - __popc(l)) & 3;
        float val = (d == 0) ? ar : (d == 1) ? -ai : (d == 2) ? -ar : ai;
        float wgt = (k == l) ? 1.f : 2.f;
        int pidx = k * 16 - (k * (k - 1)) / 2 + (l - k);
        g_B[pidx * 8 + i] = wgt * val;
    }
}

// ---------------------------------------------------------------------------
// Main kernel: 1 thread per sample. r = kron of 4 (cos, sin) 2-vectors;
// out_i = sum over 136 packed pairs B_i[p] * r_k * r_l.
// ---------------------------------------------------------------------------
__global__ void __launch_bounds__(256) qmain(const float* __restrict__ x,
                                             float* __restrict__ out) {
    __shared__ __align__(16) float Bs[NPAIR * 8];
    int t = threadIdx.x;
    for (int idx = t; idx < NPAIR * 8; idx += 256)
        Bs[idx] = g_B[idx];
    __syncthreads();

    int b = blockIdx.x * 256 + t;
    float4 xv = reinterpret_cast<const float4*>(x)[b];

    const float QP = 0.78539816339744831f;  // pi/4 (half of (x+1)*pi/2)
    float c0, s0, c1, s1, c2, s2, c3, s3;
    __sincosf((xv.x + 1.f) * QP, &s0, &c0);
    __sincosf((xv.y + 1.f) * QP, &s1, &c1);
    __sincosf((xv.z + 1.f) * QP, &s2, &c2);
    __sincosf((xv.w + 1.f) * QP, &s3, &c3);

    float r01[4] = {c0 * c1, c0 * s1, s0 * c1, s0 * s1};
    float r23[4] = {c2 * c3, c2 * s3, s2 * c3, s2 * s3};
    float r[16];
#pragma unroll
    for (int n = 0; n < 16; ++n) r[n] = r01[n >> 2] * r23[n & 3];

    float acc0 = 0.f, acc1 = 0.f, acc2 = 0.f, acc3 = 0.f;
    float acc4 = 0.f, acc5 = 0.f, acc6 = 0.f, acc7 = 0.f;
    int cnt = 0;
#pragma unroll
    for (int k = 0; k < 16; ++k) {
        float rk = r[k];
#pragma unroll
        for (int l = k; l < 16; ++l) {
            float p = rk * r[l];
            float4 b0 = *reinterpret_cast<const float4*>(&Bs[cnt * 8]);
            float4 b1 = *reinterpret_cast<const float4*>(&Bs[cnt * 8 + 4]);
            acc0 += b0.x * p; acc1 += b0.y * p;
            acc2 += b0.z * p; acc3 += b0.w * p;
            acc4 += b1.x * p; acc5 += b1.y * p;
            acc6 += b1.z * p; acc7 += b1.w * p;
            ++cnt;
        }
    }

    float4* o = reinterpret_cast<float4*>(out + (size_t)b * 8);
    o[0] = make_float4(acc0, acc1, acc2, acc3);
    o[1] = make_float4(acc4, acc5, acc6, acc7);
}

// ---------------------------------------------------------------------------
extern "C" void kernel_launch(void* const* d_in, const int* in_sizes, int n_in,
                              void* d_out, int out_size) {
    const float* x = (const float*)d_in[0];        // (65536, 4)
    const float* params = (const float*)d_in[1];   // (2, 8, 3)
    float* out = (float*)d_out;                    // (65536, 8)

    setup_columns<<<16, 128>>>(params);
    setup_B<<<16, 128>>>();
    qmain<<<BATCH / 256, 256>>>(x, out);
}